// round 13
// baseline (speedup 1.0000x reference)
#include <cuda_runtime.h>
#include <math.h>
#include <stdint.h>
#define DEV_INLINE __device__ __forceinline__

constexpr int BB=8, NTOK=1024, IND=2048, DIM=512, NH=8, DHD=64, DEPTH=2, NE=4, NC=10;
constexpr int SEQ=NTOK+1, BS=BB*SEQ, M0=BB*NTOK, QD=3*DIM;
constexpr long TSZ=(long)BS*DIM, QKVSZ=(long)BS*QD, SS=(long)SEQ*SEQ;
constexpr int NSLICE=NE*BB*NH;

__device__ float g_R[(size_t)M0*DIM];
__device__ float g_rmean[BB*DIM];
__device__ float g_gsoft[BB*NE];
__device__ float g_t[(size_t)NE*TSZ];
__device__ float g_h[(size_t)NE*TSZ];
__device__ float g_qkv[(size_t)NE*QKVSZ];
__device__ float g_sc[(size_t)NSLICE*SS];
__device__ float g_ao[(size_t)NE*TSZ];
__device__ float g_u[(size_t)NE*TSZ];
__device__ float g_late[NE*BB*DIM];
__device__ float g_loge[NE*BB*NC];

DEV_INLINE float gelu_f(float x){return 0.5f*x*(1.f+tanhf(0.7978845608028654f*(x+0.044715f*x*x*x)));}
DEV_INLINE float brsum(float v,float*sm){
    #pragma unroll
    for(int o=16;o;o>>=1)v+=__shfl_xor_sync(0xffffffffu,v,o);
    int t=threadIdx.x;if((t&31)==0)sm[t>>5]=v;__syncthreads();
    if(t<32){float z=(t<(int)(blockDim.x>>5))?sm[t]:0.f;
        #pragma unroll
        for(int o=4;o;o>>=1)z+=__shfl_xor_sync(0xffffffffu,z,o);
        if(t==0)sm[0]=z;}
    __syncthreads();float r=sm[0];__syncthreads();return r;}
DEV_INLINE float brmax(float v,float*sm){
    #pragma unroll
    for(int o=16;o;o>>=1)v=fmaxf(v,__shfl_xor_sync(0xffffffffu,v,o));
    int t=threadIdx.x;if((t&31)==0)sm[t>>5]=v;__syncthreads();
    if(t<32){float z=(t<(int)(blockDim.x>>5))?sm[t]:-1e30f;
        #pragma unroll
        for(int o=4;o;o>>=1)z=fmaxf(z,__shfl_xor_sync(0xffffffffu,z,o));
        if(t==0)sm[0]=z;}
    __syncthreads();float r=sm[0];__syncthreads();return r;}

// ======== big-tile fp32 SIMT GEMM: 256xBN CTA tile, BK=8, 256 threads ========
// C[M,N] = act(alpha*A[M,K]@op(B) + bias + res). TRANSB: B is [N,K].
// Thread grid 16x16; per-thread micro-tile: SM stripes x 4 rows, SN stripes x 4 cols
// (stripe stride 64). res may alias C (no restrict on res).
template<int BN,int SN,bool TRANSB,int ACT,bool BIAS,bool RES,bool SHIFT>
DEV_INLINE void gemm_big(const float* __restrict__ A,long lda,
                         const float* __restrict__ Bm,long ldb,
                         const float* __restrict__ bias,const float* res,long ldres,
                         float* C,long ldc,int M,int N,int K,float alpha){
    constexpr int BM=256, SM=4, BK=8;
    __shared__ __align__(16) float as[2][BK*BM];
    __shared__ __align__(16) float bs[2][BK*BN];
    const int tid=threadIdx.x;
    const int tr=tid>>4, tc=tid&15;
    const int row0=blockIdx.y*BM, col0=blockIdx.x*BN;

    float acc[SM][SN][4][4];
    #pragma unroll
    for(int s=0;s<SM;s++)
        #pragma unroll
        for(int s2=0;s2<SN;s2++)
            #pragma unroll
            for(int i=0;i<4;i++)
                #pragma unroll
                for(int j=0;j<4;j++) acc[s][s2][i][j]=0.f;

    float ra[8];             // A: 256x8 / 256thr = 8 scalars
    float rb[BN/32];         // B: 8xBN / 256thr = BN/32 scalars
    const int aar=(tid*2)>>1;            // not used; keep simple below

    // ---- fetch helpers (inline) ----
    auto fetchA=[&](int kt){
        #pragma unroll
        for(int q=0;q<2;q++){
            int u=tid+q*256; int ar=u>>1, ac=(u&1)*4;
            int gr=row0+ar;
            #pragma unroll
            for(int j=0;j<4;j++){
                int gk=kt+ac+j;
                ra[q*4+j]=(gr<M&&gk<K)?A[(long)gr*lda+gk]:0.f;
            }
        }
    };
    auto storeA=[&](int b){
        #pragma unroll
        for(int q=0;q<2;q++){
            int u=tid+q*256; int ar=u>>1, ac=(u&1)*4;
            #pragma unroll
            for(int j=0;j<4;j++) as[b][(ac+j)*BM+ar]=ra[q*4+j];
        }
    };
    auto fetchB=[&](int kt){
        if(!TRANSB){
            int br=tid>>5, bc=(tid&31)*(BN/32);
            #pragma unroll
            for(int j=0;j<BN/32;j++){
                int gk=kt+br, gc=col0+bc+j;
                rb[j]=(gk<K&&gc<N)?Bm[(long)gk*ldb+gc]:0.f;
            }
        }else{ // BN==128 only
            int bn=tid>>1, bk=(tid&1)*4;
            #pragma unroll
            for(int j=0;j<4;j++){
                int gn=col0+bn, gk=kt+bk+j;
                rb[j]=(gn<N&&gk<K)?Bm[(long)gn*ldb+gk]:0.f;
            }
        }
    };
    auto storeB=[&](int b){
        if(!TRANSB){
            int br=tid>>5, bc=(tid&31)*(BN/32);
            #pragma unroll
            for(int j=0;j<BN/32;j++) bs[b][br*BN+bc+j]=rb[j];
        }else{
            int bn=tid>>1, bk=(tid&1)*4;
            #pragma unroll
            for(int j=0;j<4;j++) bs[b][(bk+j)*BN+bn]=rb[j];
        }
    };

    const int T=(K+BK-1)/BK;
    fetchA(0); fetchB(0);
    storeA(0); storeB(0);
    __syncthreads();
    for(int t=0;t<T;t++){
        int cur=t&1;
        if(t+1<T){ fetchA((t+1)*BK); fetchB((t+1)*BK); }
        #pragma unroll
        for(int kk=0;kk<BK;kk++){
            float av[SM][4], bv[SN][4];
            #pragma unroll
            for(int s=0;s<SM;s++)
                *(float4*)av[s]=*(const float4*)&as[cur][kk*BM+s*64+tr*4];
            #pragma unroll
            for(int s2=0;s2<SN;s2++)
                *(float4*)bv[s2]=*(const float4*)&bs[cur][kk*BN+s2*64+tc*4];
            #pragma unroll
            for(int s=0;s<SM;s++)
                #pragma unroll
                for(int s2=0;s2<SN;s2++)
                    #pragma unroll
                    for(int i=0;i<4;i++)
                        #pragma unroll
                        for(int j=0;j<4;j++)
                            acc[s][s2][i][j]+=av[s][i]*bv[s2][j];
        }
        if(t+1<T){ storeA((t+1)&1); storeB((t+1)&1); }
        __syncthreads();
    }

    #pragma unroll
    for(int s=0;s<SM;s++){
        #pragma unroll
        for(int i=0;i<4;i++){
            int r=row0+s*64+tr*4+i;
            if(r>=M) continue;
            long orow=SHIFT?((long)r+r/1024+1):(long)r;
            #pragma unroll
            for(int s2=0;s2<SN;s2++){
                #pragma unroll
                for(int j=0;j<4;j++){
                    int c=col0+s2*64+tc*4+j;
                    if(c>=N) continue;
                    float v=acc[s][s2][i][j]*alpha;
                    if(BIAS)v+=bias[c];
                    if(RES)v+=res[orow*ldres+c];
                    if(ACT==1)v=fmaxf(v,0.f);else if(ACT==2)v=gelu_f(v);
                    C[orow*ldc+c]=v;
                }
            }
        }
    }
}

// ---------------- GEMM wrapper kernels (R1-proven index math) ----------------
__global__ void __launch_bounds__(256,1) k_router_proj(const float*x,const float*Wr,const float*br){
    gemm_big<128,2,false,1,true,false,false>(x,IND,Wr,DIM,br,nullptr,0,
        g_R,DIM,M0,DIM,IND,1.f);}
__global__ void __launch_bounds__(256,1) k_expert_proj(const float*x,const float*Wp,const float*bp){
    long e=blockIdx.z;
    gemm_big<128,2,false,1,true,false,true>(x,IND,Wp+e*IND*DIM,DIM,bp+e*DIM,nullptr,0,
        g_t+e*TSZ,DIM,M0,DIM,IND,1.f);}
__global__ void __launch_bounds__(256,1) k_qkv(const float*Wqkv,const float*bqkv,int l){
    long e=blockIdx.z, we=e*DEPTH+l;
    gemm_big<128,2,false,0,true,false,false>(g_h+e*TSZ,DIM,Wqkv+we*DIM*QD,QD,bqkv+we*QD,nullptr,0,
        g_qkv+e*QKVSZ,QD,BS,QD,DIM,1.f);}
__global__ void __launch_bounds__(256,1) k_scores(){
    int z=blockIdx.z;
    int e=z/(BB*NH), b=(z/NH)%BB, h=z%NH;
    const float* base=g_qkv+(long)e*QKVSZ+(long)b*SEQ*QD;
    gemm_big<128,2,true,0,false,false,false>(base+h*DHD,QD,base+DIM+h*DHD,QD,nullptr,nullptr,0,
        g_sc+(long)z*SS,SEQ,SEQ,SEQ,DHD,0.125f);}
__global__ void __launch_bounds__(256,1) k_av(){
    int z=blockIdx.z;
    int e=z/(BB*NH), b=(z/NH)%BB, h=z%NH;
    gemm_big<64,1,false,0,false,false,false>(g_sc+(long)z*SS,SEQ,
        g_qkv+(long)e*QKVSZ+(long)b*SEQ*QD+2*DIM+h*DHD,QD,nullptr,nullptr,0,
        g_ao+(long)e*TSZ+(long)b*SEQ*DIM+h*DHD,DIM,SEQ,DHD,SEQ,1.f);}
__global__ void __launch_bounds__(256,1) k_oproj(const float*Wo,const float*bo,int l){
    long e=blockIdx.z, we=e*DEPTH+l;
    gemm_big<128,2,false,0,true,true,false>(g_ao+e*TSZ,DIM,Wo+we*DIM*DIM,DIM,bo+we*DIM,
        g_t+e*TSZ,DIM,g_t+e*TSZ,DIM,BS,DIM,DIM,1.f);}
__global__ void __launch_bounds__(256,1) k_mlp1(const float*W1,const float*b1,int l){
    long e=blockIdx.z, we=e*DEPTH+l;
    gemm_big<128,2,false,2,true,false,false>(g_h+e*TSZ,DIM,W1+we*DIM*DIM,DIM,b1+we*DIM,nullptr,0,
        g_u+e*TSZ,DIM,BS,DIM,DIM,1.f);}
__global__ void __launch_bounds__(256,1) k_mlp2(const float*W2,const float*b2,int l){
    long e=blockIdx.z, we=e*DEPTH+l;
    gemm_big<128,2,false,0,true,true,false>(g_u+e*TSZ,DIM,W2+we*DIM*DIM,DIM,b2+we*DIM,
        g_t+e*TSZ,DIM,g_t+e*TSZ,DIM,BS,DIM,DIM,1.f);}

// ---------------- non-GEMM kernels (R1 verbatim) ----------------
__global__ void __launch_bounds__(512) k_set_cls(const float*cls){
    int b=blockIdx.x,e=blockIdx.y;
    g_t[(size_t)e*TSZ+(size_t)b*SEQ*DIM+threadIdx.x]=cls[e*DIM+threadIdx.x];}
__global__ void __launch_bounds__(256) k_ln(const float*g,const float*bb,long gE,int fin){
    __shared__ float sm[8];
    int e=blockIdx.y;const float*xp;float*op;
    if(fin==0){long row=blockIdx.x;xp=g_t+(long)e*TSZ+row*DIM;op=g_h+(long)e*TSZ+row*DIM;}
    else{int b=blockIdx.x;xp=g_t+(long)e*TSZ+(long)b*SEQ*DIM;op=g_late+((long)e*BB+b)*DIM;}
    const float*gp=g+e*gE;const float*bp=bb+e*gE;
    int t=threadIdx.x;
    float x0=xp[t],x1=xp[t+256];
    float s=brsum(x0+x1,sm), sq=brsum(x0*x0+x1*x1,sm);
    float m=s*(1.f/DIM), v=sq*(1.f/DIM)-m*m, inv=rsqrtf(v+1e-5f);
    op[t]=(x0-m)*inv*gp[t]+bp[t];
    op[t+256]=(x1-m)*inv*gp[t+256]+bp[t+256];}
__global__ void __launch_bounds__(256) k_softmax(){
    __shared__ float sm[8];
    int e=blockIdx.y;long row=blockIdx.x;
    float*p=g_sc+(long)e*((long)BB*NH*SS)+row*SEQ;
    int t=threadIdx.x;float v[5],mx=-1e30f;
    #pragma unroll
    for(int i=0;i<5;i++){int idx=t+i*256;v[i]=(idx<SEQ)?p[idx]:-1e30f;mx=fmaxf(mx,v[i]);}
    mx=brmax(mx,sm);
    float s=0.f;
    #pragma unroll
    for(int i=0;i<5;i++){int idx=t+i*256;if(idx<SEQ){v[i]=__expf(v[i]-mx);s+=v[i];}else v[i]=0.f;}
    s=brsum(s,sm);float inv=1.f/s;
    #pragma unroll
    for(int i=0;i<5;i++){int idx=t+i*256;if(idx<SEQ)p[idx]=v[i]*inv;}}
__global__ void __launch_bounds__(512) k_meanpool(){
    int b=blockIdx.x,d=threadIdx.x;
    const float*p=g_R+(long)b*NTOK*DIM+d;float s=0.f;
    for(int n=0;n<NTOK;n++)s+=p[(long)n*DIM];
    g_rmean[b*DIM+d]=s*(1.f/NTOK);}
__global__ void __launch_bounds__(32) k_router_head(const float*Wrf,const float*brf){
    __shared__ float lg[BB][NE];
    int t=threadIdx.x;
    if(t<BB*NE){int b=t/NE,e=t%NE;float s=brf[e];
        for(int d=0;d<DIM;d++)s+=g_rmean[b*DIM+d]*Wrf[d*NE+e];
        lg[b][e]=s;}
    __syncthreads();
    if(t<BB){float mx=-1e30f;
        for(int e=0;e<NE;e++)mx=fmaxf(mx,lg[t][e]);
        float ex[NE],sum=0.f;
        for(int e=0;e<NE;e++){ex[e]=__expf(lg[t][e]-mx);sum+=ex[e];}
        for(int e=0;e<NE;e++)g_gsoft[t*NE+e]=ex[e]/sum;}}
__global__ void __launch_bounds__(320) k_head(const float*Wh,const float*bh){
    int eb=blockIdx.x,e=eb/BB;
    int w=threadIdx.x>>5,lane=threadIdx.x&31;
    const float*lat=g_late+(long)eb*DIM;const float*wp=Wh+(long)e*DIM*NC;
    float s=0.f;
    for(int d=lane;d<DIM;d+=32)s+=lat[d]*wp[d*NC+w];
    #pragma unroll
    for(int o=16;o;o>>=1)s+=__shfl_xor_sync(0xffffffffu,s,o);
    if(lane==0)g_loge[eb*NC+w]=s+bh[e*NC+w];}
__global__ void __launch_bounds__(256) k_combine(float*out,int n){
    int idx=blockIdx.x*256+threadIdx.x;if(idx>=n)return;
    if(idx<BB*DIM){int b=idx/DIM,d=idx%DIM;float s=0.f;
        for(int e=0;e<NE;e++)s+=g_gsoft[b*NE+e]*g_late[(e*BB+b)*DIM+d];out[idx]=s;}
    else if(idx<BB*DIM+BB*NC){int i=idx-BB*DIM,b=i/NC,c=i%NC;float s=0.f;
        for(int e=0;e<NE;e++)s+=g_gsoft[b*NE+e]*g_loge[(e*BB+b)*NC+c];out[idx]=s;}
    else if(idx<BB*DIM+BB*NC+BB*NE)out[idx]=g_gsoft[idx-BB*DIM-BB*NC];
    else out[idx]=0.f;}

extern "C" void kernel_launch(void* const* d_in,const int* in_sizes,int n_in,void* d_out,int out_size){
    const float*x=(const float*)d_in[0],*Wr=(const float*)d_in[1],*br=(const float*)d_in[2];
    const float*Wrf=(const float*)d_in[3],*brf=(const float*)d_in[4];
    const float*Wp=(const float*)d_in[5],*bp=(const float*)d_in[6],*cls=(const float*)d_in[7];
    const float*ln1g=(const float*)d_in[8],*ln1b=(const float*)d_in[9];
    const float*Wqkv=(const float*)d_in[10],*bqkv=(const float*)d_in[11];
    const float*Wo=(const float*)d_in[12],*bo=(const float*)d_in[13];
    const float*ln2g=(const float*)d_in[14],*ln2b=(const float*)d_in[15];
    const float*W1=(const float*)d_in[16],*b1=(const float*)d_in[17];
    const float*W2=(const float*)d_in[18],*b2=(const float*)d_in[19];
    const float*lnfg=(const float*)d_in[20],*lnfb=(const float*)d_in[21];
    const float*Wh=(const float*)d_in[22],*bh=(const float*)d_in[23];
    float*out=(float*)d_out;

    const int gyM0=M0/256;                 // 32
    const int gyBS=(BS+255)/256;           // 33
    const int gySm=(SEQ+255)/256;          // 5
    const int gxS =(SEQ+127)/128;          // 9

    k_router_proj<<<dim3(DIM/128,gyM0),256>>>(x,Wr,br);
    k_meanpool<<<BB,DIM>>>();
    k_router_head<<<1,32>>>(Wrf,brf);

    k_expert_proj<<<dim3(DIM/128,gyM0,NE),256>>>(x,Wp,bp);
    k_set_cls<<<dim3(BB,NE),DIM>>>(cls);

    for(int l=0;l<DEPTH;l++){
        k_ln<<<dim3(BS,NE),256>>>(ln1g+l*DIM,ln1b+l*DIM,(long)DEPTH*DIM,0);
        k_qkv<<<dim3(QD/128,gyBS,NE),256>>>(Wqkv,bqkv,l);
        k_scores<<<dim3(gxS,gySm,NSLICE),256>>>();
        k_softmax<<<dim3(BB*NH*SEQ,NE),256>>>();
        k_av<<<dim3(1,gySm,NSLICE),256>>>();
        k_oproj<<<dim3(DIM/128,gyBS,NE),256>>>(Wo,bo,l);
        k_ln<<<dim3(BS,NE),256>>>(ln2g+l*DIM,ln2b+l*DIM,(long)DEPTH*DIM,0);
        k_mlp1<<<dim3(DIM/128,gyBS,NE),256>>>(W1,b1,l);
        k_mlp2<<<dim3(DIM/128,gyBS,NE),256>>>(W2,b2,l);
    }
    k_ln<<<dim3(BB,NE),256>>>(lnfg,lnfb,(long)DIM,1);
    k_head<<<NE*BB,320>>>(Wh,bh);
    k_combine<<<(out_size+255)/256,256>>>(out,out_size);
}

// round 14
// speedup vs baseline: 1.2569x; 1.2569x over previous
#include <cuda_runtime.h>
#include <cuda_bf16.h>
#include <mma.h>
#include <math.h>
#include <stdint.h>
#define DEV_INLINE __device__ __forceinline__
typedef __nv_bfloat16 bf16;
using namespace nvcuda;

constexpr int BB=8, NTOK=1024, IND=2048, DIM=512, NH=8, DHD=64, DEPTH=2, NE=4, NC=10;
constexpr int SEQ=NTOK+1, BS=BB*SEQ, M0=BB*NTOK, QD=3*DIM;
constexpr long TSZ=(long)BS*DIM, QKVSZ=(long)BS*QD, SS=(long)SEQ*SEQ;
constexpr int NSLICE=NE*BB*NH;

__device__ float g_R[(size_t)M0*DIM];
__device__ float g_rmean[BB*DIM];
__device__ float g_gsoft[BB*NE];
__device__ float g_t[(size_t)NE*TSZ];
__device__ float g_h[(size_t)NE*TSZ];
__device__ float g_qkv[(size_t)NE*QKVSZ];
__device__ float g_sc[(size_t)NSLICE*SS];
__device__ float g_ao[(size_t)NE*TSZ];
__device__ float g_u[(size_t)NE*TSZ];
__device__ float g_late[NE*BB*DIM];
__device__ float g_loge[NE*BB*NC];

DEV_INLINE float gelu_f(float x){return 0.5f*x*(1.f+tanhf(0.7978845608028654f*(x+0.044715f*x*x*x)));}
DEV_INLINE float brsum(float v,float*sm){
    #pragma unroll
    for(int o=16;o;o>>=1)v+=__shfl_xor_sync(0xffffffffu,v,o);
    int t=threadIdx.x;if((t&31)==0)sm[t>>5]=v;__syncthreads();
    if(t<32){float z=(t<(int)(blockDim.x>>5))?sm[t]:0.f;
        #pragma unroll
        for(int o=4;o;o>>=1)z+=__shfl_xor_sync(0xffffffffu,z,o);
        if(t==0)sm[0]=z;}
    __syncthreads();float r=sm[0];__syncthreads();return r;}
DEV_INLINE float brmax(float v,float*sm){
    #pragma unroll
    for(int o=16;o;o>>=1)v=fmaxf(v,__shfl_xor_sync(0xffffffffu,v,o));
    int t=threadIdx.x;if((t&31)==0)sm[t>>5]=v;__syncthreads();
    if(t<32){float z=(t<(int)(blockDim.x>>5))?sm[t]:-1e30f;
        #pragma unroll
        for(int o=4;o;o>>=1)z=fmaxf(z,__shfl_xor_sync(0xffffffffu,z,o));
        if(t==0)sm[0]=z;}
    __syncthreads();float r=sm[0];__syncthreads();return r;}

// ======== fp32 GEMM: 128xBN CTA tile, BK=8, 128 threads, 16xSNx4 per thread ========
// C[M,N]=act(alpha*A@op(B)+bias+res). TRANSB: B is [N,K]. res may alias C.
template<int BN,int SN,bool TRANSB,int ACT,bool BIAS,bool RES,bool SHIFT>
DEV_INLINE void gemm_big(const float* __restrict__ A,long lda,
                         const float* __restrict__ Bm,long ldb,
                         const float* __restrict__ bias,const float* res,long ldres,
                         float* C,long ldc,int M,int N,int K,float alpha){
    constexpr int BM=128, SM=4, BK=8, ASTR=BM+4;
    __shared__ __align__(16) float as[2][BK*ASTR];
    __shared__ __align__(16) float bs[2][BK*BN];
    const int tid=threadIdx.x;
    const int tr=tid>>4, tc=tid&15;                 // 8 x 16
    const int row0=blockIdx.y*BM, col0=blockIdx.x*BN;
    const bool laligned=((lda&3)==0);

    float acc[SM][SN][4][4];
    #pragma unroll
    for(int s=0;s<SM;s++)
        #pragma unroll
        for(int s2=0;s2<SN;s2++)
            #pragma unroll
            for(int i=0;i<4;i++)
                #pragma unroll
                for(int j=0;j<4;j++) acc[s][s2][i][j]=0.f;

    float4 ra[2], rb[2];

    auto fetchA=[&](int kt){
        #pragma unroll
        for(int q=0;q<2;q++){
            int u=tid+q*128; int ar=u>>1, ac=(u&1)*4;
            int gr=row0+ar, gk=kt+ac;
            float4 v=make_float4(0.f,0.f,0.f,0.f);
            if(gr<M){
                if(laligned && gk+3<K) v=*(const float4*)(A+(long)gr*lda+gk);
                else{
                    float* vp=(float*)&v;
                    #pragma unroll
                    for(int j=0;j<4;j++) if(gk+j<K) vp[j]=A[(long)gr*lda+gk+j];
                }
            }
            ra[q]=v;
        }
    };
    auto storeA=[&](int b){
        #pragma unroll
        for(int q=0;q<2;q++){
            int u=tid+q*128; int ar=u>>1, ac=(u&1)*4;
            const float* vp=(const float*)&ra[q];
            #pragma unroll
            for(int j=0;j<4;j++) as[b][(ac+j)*ASTR+ar]=vp[j];
        }
    };
    auto fetchB=[&](int kt){
        if(!TRANSB){
            #pragma unroll
            for(int q=0;q<(BN==128?2:1);q++){
                int u=tid+q*128;
                int br,bc;
                if(BN==128){ br=u>>5; bc=(u&31)*4; }
                else       { br=u>>4; bc=(u&15)*4; }   // BN==64, threads >=128 skip via u<128
                float4 v=make_float4(0.f,0.f,0.f,0.f);
                int gk=kt+br, gc=col0+bc;
                if((BN==128 || u<128) && gk<K){
                    if(gc+3<N) v=*(const float4*)(Bm+(long)gk*ldb+gc);
                    else{
                        float* vp=(float*)&v;
                        #pragma unroll
                        for(int j=0;j<4;j++) if(gc+j<N) vp[j]=Bm[(long)gk*ldb+gc+j];
                    }
                }
                rb[q]=v;
            }
        }else{ // BN==128
            #pragma unroll
            for(int q=0;q<2;q++){
                int u=tid+q*128;
                int bn=u>>1, bk=(u&1)*4;
                int gn=col0+bn, gk=kt+bk;
                float4 v=make_float4(0.f,0.f,0.f,0.f);
                if(gn<N){
                    if(gk+3<K) v=*(const float4*)(Bm+(long)gn*ldb+gk);
                    else{
                        float* vp=(float*)&v;
                        #pragma unroll
                        for(int j=0;j<4;j++) if(gk+j<K) vp[j]=Bm[(long)gn*ldb+gk+j];
                    }
                }
                rb[q]=v;
            }
        }
    };
    auto storeB=[&](int b){
        if(!TRANSB){
            #pragma unroll
            for(int q=0;q<(BN==128?2:1);q++){
                int u=tid+q*128;
                if(BN==128){ int br=u>>5, bc=(u&31)*4; *(float4*)&bs[b][br*BN+bc]=rb[q]; }
                else if(u<128){ int br=u>>4, bc=(u&15)*4; *(float4*)&bs[b][br*BN+bc]=rb[q]; }
            }
        }else{
            #pragma unroll
            for(int q=0;q<2;q++){
                int u=tid+q*128;
                int bn=u>>1, bk=(u&1)*4;
                const float* vp=(const float*)&rb[q];
                #pragma unroll
                for(int j=0;j<4;j++) bs[b][(bk+j)*BN+bn]=vp[j];
            }
        }
    };

    const int T=(K+BK-1)/BK;
    fetchA(0); fetchB(0);
    storeA(0); storeB(0);
    __syncthreads();
    for(int t=0;t<T;t++){
        int cur=t&1;
        if(t+1<T){ fetchA((t+1)*BK); fetchB((t+1)*BK); }
        #pragma unroll
        for(int kk=0;kk<BK;kk++){
            float av[SM][4], bv[SN][4];
            #pragma unroll
            for(int s=0;s<SM;s++)
                *(float4*)av[s]=*(const float4*)&as[cur][kk*ASTR+s*32+tr*4];
            #pragma unroll
            for(int s2=0;s2<SN;s2++)
                *(float4*)bv[s2]=*(const float4*)&bs[cur][kk*BN+s2*64+tc*4];
            #pragma unroll
            for(int s=0;s<SM;s++)
                #pragma unroll
                for(int s2=0;s2<SN;s2++)
                    #pragma unroll
                    for(int i=0;i<4;i++)
                        #pragma unroll
                        for(int j=0;j<4;j++)
                            acc[s][s2][i][j]+=av[s][i]*bv[s2][j];
        }
        if(t+1<T){ storeA((t+1)&1); storeB((t+1)&1); }
        __syncthreads();
    }

    #pragma unroll
    for(int s=0;s<SM;s++){
        #pragma unroll
        for(int i=0;i<4;i++){
            int r=row0+s*32+tr*4+i;
            if(r>=M) continue;
            long orow=SHIFT?((long)r+r/1024+1):(long)r;
            #pragma unroll
            for(int s2=0;s2<SN;s2++){
                #pragma unroll
                for(int j=0;j<4;j++){
                    int c=col0+s2*64+tc*4+j;
                    if(c>=N) continue;
                    float v=acc[s][s2][i][j]*alpha;
                    if(BIAS)v+=bias[c];
                    if(RES)v+=res[orow*ldres+c];
                    if(ACT==1)v=fmaxf(v,0.f);else if(ACT==2)v=gelu_f(v);
                    C[orow*ldc+c]=v;
                }
            }
        }
    }
}

__global__ void __launch_bounds__(128,2) k_router_proj(const float*x,const float*Wr,const float*br){
    gemm_big<128,2,false,1,true,false,false>(x,IND,Wr,DIM,br,nullptr,0,g_R,DIM,M0,DIM,IND,1.f);}
__global__ void __launch_bounds__(128,2) k_expert_proj(const float*x,const float*Wp,const float*bp){
    long e=blockIdx.z;
    gemm_big<128,2,false,1,true,false,true>(x,IND,Wp+e*IND*DIM,DIM,bp+e*DIM,nullptr,0,
        g_t+e*TSZ,DIM,M0,DIM,IND,1.f);}
__global__ void __launch_bounds__(128,2) k_qkv(const float*Wqkv,const float*bqkv,int l){
    long e=blockIdx.z, we=e*DEPTH+l;
    gemm_big<128,2,false,0,true,false,false>(g_h+e*TSZ,DIM,Wqkv+we*DIM*QD,QD,bqkv+we*QD,nullptr,0,
        g_qkv+e*QKVSZ,QD,BS,QD,DIM,1.f);}
__global__ void __launch_bounds__(128,2) k_scores(){
    int z=blockIdx.z;
    int e=z/(BB*NH), b=(z/NH)%BB, h=z%NH;
    const float* base=g_qkv+(long)e*QKVSZ+(long)b*SEQ*QD;
    gemm_big<128,2,true,0,false,false,false>(base+h*DHD,QD,base+DIM+h*DHD,QD,nullptr,nullptr,0,
        g_sc+(long)z*SS,SEQ,SEQ,SEQ,DHD,0.125f);}
__global__ void __launch_bounds__(128,2) k_av(){
    int z=blockIdx.z;
    int e=z/(BB*NH), b=(z/NH)%BB, h=z%NH;
    gemm_big<64,1,false,0,false,false,false>(g_sc+(long)z*SS,SEQ,
        g_qkv+(long)e*QKVSZ+(long)b*SEQ*QD+2*DIM+h*DHD,QD,nullptr,nullptr,0,
        g_ao+(long)e*TSZ+(long)b*SEQ*DIM+h*DHD,DIM,SEQ,DHD,SEQ,1.f);}
__global__ void __launch_bounds__(128,2) k_oproj(const float*Wo,const float*bo,int l){
    long e=blockIdx.z, we=e*DEPTH+l;
    gemm_big<128,2,false,0,true,true,false>(g_ao+e*TSZ,DIM,Wo+we*DIM*DIM,DIM,bo+we*DIM,
        g_t+e*TSZ,DIM,g_t+e*TSZ,DIM,BS,DIM,DIM,1.f);}
__global__ void __launch_bounds__(128,2) k_mlp1(const float*W1,const float*b1,int l){
    long e=blockIdx.z, we=e*DEPTH+l;
    gemm_big<128,2,false,2,true,false,false>(g_h+e*TSZ,DIM,W1+we*DIM*DIM,DIM,b1+we*DIM,nullptr,0,
        g_u+e*TSZ,DIM,BS,DIM,DIM,1.f);}
__global__ void __launch_bounds__(128,2) k_mlp2(const float*W2,const float*b2,int l){
    long e=blockIdx.z, we=e*DEPTH+l;
    gemm_big<128,2,false,0,true,true,false>(g_u+e*TSZ,DIM,W2+we*DIM*DIM,DIM,b2+we*DIM,
        g_t+e*TSZ,DIM,g_t+e*TSZ,DIM,BS,DIM,DIM,1.f);}

// ======== wmma diagnostic: expert-proj (no SHIFT) into g_u scratch ========
__global__ void __launch_bounds__(256) g_wdiag(const float*x,const float*Wp,const float*bp){
    constexpr int STRA=24, STRB=136;
    __shared__ __align__(32) bf16 sAh[128*STRA], sAl[128*STRA];
    __shared__ __align__(32) bf16 sBh[16*STRB], sBl[16*STRB];
    __shared__ __align__(32) float stg[8][256];
    long e=blockIdx.z;
    const float* A=x;
    const float* W=Wp+e*IND*DIM;
    const int tid=threadIdx.x, w=tid>>5, l=tid&31;
    const int row0=blockIdx.y*128, col0=blockIdx.x*128;

    wmma::fragment<wmma::accumulator,16,16,16,float> acc[8];
    #pragma unroll
    for(int nt=0;nt<8;nt++) wmma::fill_fragment(acc[nt],0.f);

    for(int kt=0;kt<IND;kt+=16){
        for(int i=tid;i<128*16;i+=256){
            int r=i>>4,k=i&15;
            float v=A[(long)(row0+r)*IND+kt+k];
            bf16 hh=__float2bfloat16(v);
            sAh[r*STRA+k]=hh;
            sAl[r*STRA+k]=__float2bfloat16(v-__bfloat162float(hh));
        }
        for(int i=tid;i<16*128;i+=256){
            int k=i>>7,n=i&127;
            float v=W[(long)(kt+k)*DIM+col0+n];
            bf16 hh=__float2bfloat16(v);
            sBh[k*STRB+n]=hh;
            sBl[k*STRB+n]=__float2bfloat16(v-__bfloat162float(hh));
        }
        __syncthreads();
        wmma::fragment<wmma::matrix_a,16,16,16,bf16,wmma::row_major> fah,fal;
        wmma::load_matrix_sync(fah,&sAh[w*16*STRA],STRA);
        wmma::load_matrix_sync(fal,&sAl[w*16*STRA],STRA);
        #pragma unroll
        for(int nt=0;nt<8;nt++){
            wmma::fragment<wmma::matrix_b,16,16,16,bf16,wmma::row_major> fbh,fbl;
            wmma::load_matrix_sync(fbh,&sBh[nt*16],STRB);
            wmma::load_matrix_sync(fbl,&sBl[nt*16],STRB);
            wmma::mma_sync(acc[nt],fah,fbh,acc[nt]);
            wmma::mma_sync(acc[nt],fah,fbl,acc[nt]);
            wmma::mma_sync(acc[nt],fal,fbh,acc[nt]);
        }
        __syncthreads();
    }
    #pragma unroll
    for(int nt=0;nt<8;nt++){
        wmma::store_matrix_sync(stg[w],acc[nt],16,wmma::mem_row_major);
        __syncwarp();
        int rr=l>>1, c0=(l&1)*8;
        int r=row0+w*16+rr;
        #pragma unroll
        for(int j=0;j<8;j++){
            int cc=col0+nt*16+c0+j;
            float v=stg[w][rr*16+c0+j]+bp[e*DIM+cc];
            g_u[e*TSZ+(long)r*DIM+cc]=fmaxf(v,0.f);
        }
        __syncwarp();
    }
}
// adopt wmma values into g_t where they agree with the fp32 result
__global__ void __launch_bounds__(256) k_adopt(){
    long n=(long)NE*M0*DIM;
    for(long idx=blockIdx.x*256L+threadIdx.x;idx<n;idx+=(long)gridDim.x*256L){
        long e=idx/((long)M0*DIM);
        long rem=idx-e*(long)M0*DIM;
        long r=rem/DIM, c=rem-r*DIM;
        long orow=r+r/1024+1;
        float fp=g_t[e*TSZ+orow*DIM+c];
        float wm=g_u[e*TSZ+r*DIM+c];
        if(fabsf(wm-fp)<=1e-3f*fabsf(fp)+1e-3f) g_t[e*TSZ+orow*DIM+c]=wm;
    }
}

// ---------------- non-GEMM kernels (proven) ----------------
__global__ void __launch_bounds__(512) k_set_cls(const float*cls){
    int b=blockIdx.x,e=blockIdx.y;
    g_t[(size_t)e*TSZ+(size_t)b*SEQ*DIM+threadIdx.x]=cls[e*DIM+threadIdx.x];}
__global__ void __launch_bounds__(256) k_ln(const float*g,const float*bb,long gE,int fin){
    __shared__ float sm[8];
    int e=blockIdx.y;const float*xp;float*op;
    if(fin==0){long row=blockIdx.x;xp=g_t+(long)e*TSZ+row*DIM;op=g_h+(long)e*TSZ+row*DIM;}
    else{int b=blockIdx.x;xp=g_t+(long)e*TSZ+(long)b*SEQ*DIM;op=g_late+((long)e*BB+b)*DIM;}
    const float*gp=g+e*gE;const float*bp=bb+e*gE;
    int t=threadIdx.x;
    float x0=xp[t],x1=xp[t+256];
    float s=brsum(x0+x1,sm), sq=brsum(x0*x0+x1*x1,sm);
    float m=s*(1.f/DIM), v=sq*(1.f/DIM)-m*m, inv=rsqrtf(v+1e-5f);
    op[t]=(x0-m)*inv*gp[t]+bp[t];
    op[t+256]=(x1-m)*inv*gp[t+256]+bp[t+256];}
__global__ void __launch_bounds__(256) k_softmax(){
    __shared__ float sm[8];
    int e=blockIdx.y;long row=blockIdx.x;
    float*p=g_sc+(long)e*((long)BB*NH*SS)+row*SEQ;
    int t=threadIdx.x;float v[5],mx=-1e30f;
    #pragma unroll
    for(int i=0;i<5;i++){int idx=t+i*256;v[i]=(idx<SEQ)?p[idx]:-1e30f;mx=fmaxf(mx,v[i]);}
    mx=brmax(mx,sm);
    float s=0.f;
    #pragma unroll
    for(int i=0;i<5;i++){int idx=t+i*256;if(idx<SEQ){v[i]=__expf(v[i]-mx);s+=v[i];}else v[i]=0.f;}
    s=brsum(s,sm);float inv=1.f/s;
    #pragma unroll
    for(int i=0;i<5;i++){int idx=t+i*256;if(idx<SEQ)p[idx]=v[i]*inv;}}
__global__ void __launch_bounds__(512) k_meanpool(){
    int b=blockIdx.x,d=threadIdx.x;
    const float*p=g_R+(long)b*NTOK*DIM+d;float s=0.f;
    for(int n=0;n<NTOK;n++)s+=p[(long)n*DIM];
    g_rmean[b*DIM+d]=s*(1.f/NTOK);}
__global__ void __launch_bounds__(32) k_router_head(const float*Wrf,const float*brf){
    __shared__ float lg[BB][NE];
    int t=threadIdx.x;
    if(t<BB*NE){int b=t/NE,e=t%NE;float s=brf[e];
        for(int d=0;d<DIM;d++)s+=g_rmean[b*DIM+d]*Wrf[d*NE+e];
        lg[b][e]=s;}
    __syncthreads();
    if(t<BB){float mx=-1e30f;
        for(int e=0;e<NE;e++)mx=fmaxf(mx,lg[t][e]);
        float ex[NE],sum=0.f;
        for(int e=0;e<NE;e++){ex[e]=__expf(lg[t][e]-mx);sum+=ex[e];}
        for(int e=0;e<NE;e++)g_gsoft[t*NE+e]=ex[e]/sum;}}
__global__ void __launch_bounds__(320) k_head(const float*Wh,const float*bh){
    int eb=blockIdx.x,e=eb/BB;
    int w=threadIdx.x>>5,lane=threadIdx.x&31;
    const float*lat=g_late+(long)eb*DIM;const float*wp=Wh+(long)e*DIM*NC;
    float s=0.f;
    for(int d=lane;d<DIM;d+=32)s+=lat[d]*wp[d*NC+w];
    #pragma unroll
    for(int o=16;o;o>>=1)s+=__shfl_xor_sync(0xffffffffu,s,o);
    if(lane==0)g_loge[eb*NC+w]=s+bh[e*NC+w];}
__global__ void __launch_bounds__(256) k_combine(float*out,int n){
    int idx=blockIdx.x*256+threadIdx.x;if(idx>=n)return;
    if(idx<BB*DIM){int b=idx/DIM,d=idx%DIM;float s=0.f;
        for(int e=0;e<NE;e++)s+=g_gsoft[b*NE+e]*g_late[(e*BB+b)*DIM+d];out[idx]=s;}
    else if(idx<BB*DIM+BB*NC){int i=idx-BB*DIM,b=i/NC,c=i%NC;float s=0.f;
        for(int e=0;e<NE;e++)s+=g_gsoft[b*NE+e]*g_loge[(e*BB+b)*NC+c];out[idx]=s;}
    else if(idx<BB*DIM+BB*NC+BB*NE)out[idx]=g_gsoft[idx-BB*DIM-BB*NC];
    else out[idx]=0.f;}

extern "C" void kernel_launch(void* const* d_in,const int* in_sizes,int n_in,void* d_out,int out_size){
    const float*x=(const float*)d_in[0],*Wr=(const float*)d_in[1],*br=(const float*)d_in[2];
    const float*Wrf=(const float*)d_in[3],*brf=(const float*)d_in[4];
    const float*Wp=(const float*)d_in[5],*bp=(const float*)d_in[6],*cls=(const float*)d_in[7];
    const float*ln1g=(const float*)d_in[8],*ln1b=(const float*)d_in[9];
    const float*Wqkv=(const float*)d_in[10],*bqkv=(const float*)d_in[11];
    const float*Wo=(const float*)d_in[12],*bo=(const float*)d_in[13];
    const float*ln2g=(const float*)d_in[14],*ln2b=(const float*)d_in[15];
    const float*W1=(const float*)d_in[16],*b1=(const float*)d_in[17];
    const float*W2=(const float*)d_in[18],*b2=(const float*)d_in[19];
    const float*lnfg=(const float*)d_in[20],*lnfb=(const float*)d_in[21];
    const float*Wh=(const float*)d_in[22],*bh=(const float*)d_in[23];
    float*out=(float*)d_out;

    const int gyM0=M0/128;                 // 64
    const int gyBS=(BS+127)/128;           // 65
    const int gyS=(SEQ+127)/128;           // 9

    k_router_proj<<<dim3(DIM/128,gyM0),128>>>(x,Wr,br);
    k_meanpool<<<BB,DIM>>>();
    k_router_head<<<1,32>>>(Wrf,brf);

    k_expert_proj<<<dim3(DIM/128,gyM0,NE),128>>>(x,Wp,bp);
    // wmma diagnostic (scratch g_u) + guarded adoption; rel_err value reports verdict
    g_wdiag<<<dim3(DIM/128,gyM0,NE),256>>>(x,Wp,bp);
    k_adopt<<<4096,256>>>();
    k_set_cls<<<dim3(BB,NE),DIM>>>(cls);

    for(int l=0;l<DEPTH;l++){
        k_ln<<<dim3(BS,NE),256>>>(ln1g+l*DIM,ln1b+l*DIM,(long)DEPTH*DIM,0);
        k_qkv<<<dim3(QD/128,gyBS,NE),128>>>(Wqkv,bqkv,l);
        k_scores<<<dim3(gyS,gyS,NSLICE),128>>>();
        k_softmax<<<dim3(BB*NH*SEQ,NE),256>>>();
        k_av<<<dim3(1,gyS,NSLICE),128>>>();
        k_oproj<<<dim3(DIM/128,gyBS,NE),128>>>(Wo,bo,l);
        k_ln<<<dim3(BS,NE),256>>>(ln2g+l*DIM,ln2b+l*DIM,(long)DEPTH*DIM,0);
        k_mlp1<<<dim3(DIM/128,gyBS,NE),128>>>(W1,b1,l);
        k_mlp2<<<dim3(DIM/128,gyBS,NE),128>>>(W2,b2,l);
    }
    k_ln<<<dim3(BB,NE),256>>>(lnfg,lnfb,(long)DIM,1);
    k_head<<<NE*BB,320>>>(Wh,bh);
    k_combine<<<(out_size+255)/256,256>>>(out,out_size);
}